// round 7
// baseline (speedup 1.0000x reference)
#include <cuda_runtime.h>
#include <cuda_bf16.h>
#include <cstdint>

// Problem (fixed): B=4,N=2048,Fin=128,H=4,Fout=32.
// Identity: softmax(scores,m).sum(m)==1  =>  out = (1+self_weight)*(x @ W).
// adj, att are dead inputs.
//
// R7: HMMA bf16 3-term split. Key change: TM 64->32, grid 512, occ 3
// (3.46 blocks/SM) so staggered blocks overlap prologue latency with MMA.

#define KDIM 128
#define NDIM 128
#define TM 32
#define TN 64
#define ASTRIDE 272   // A row: 128 bf16 = 256B data + 16 pad
#define BSTRIDE 144   // B row: 64 bf16 = 128B data + 16 pad

#define SMEM_AH 0
#define SMEM_AL (SMEM_AH + TM * ASTRIDE)        // 8704
#define SMEM_BH (SMEM_AL + TM * ASTRIDE)        // 17408
#define SMEM_BL (SMEM_BH + KDIM * BSTRIDE)      // 35840
#define SMEM_TOTAL (SMEM_BL + KDIM * BSTRIDE)   // 54272

__device__ __forceinline__ uint32_t smem_u32(const void* p) {
    uint32_t a;
    asm("{ .reg .u64 t; cvta.to.shared.u64 t, %1; cvt.u32.u64 %0, t; }"
        : "=r"(a) : "l"(p));
    return a;
}

__device__ __forceinline__ void ldsm4(uint32_t r[4], uint32_t addr) {
    asm volatile("ldmatrix.sync.aligned.m8n8.x4.shared.b16 {%0,%1,%2,%3}, [%4];"
                 : "=r"(r[0]), "=r"(r[1]), "=r"(r[2]), "=r"(r[3]) : "r"(addr));
}
__device__ __forceinline__ void ldsm4t(uint32_t r[4], uint32_t addr) {
    asm volatile("ldmatrix.sync.aligned.m8n8.x4.trans.shared.b16 {%0,%1,%2,%3}, [%4];"
                 : "=r"(r[0]), "=r"(r[1]), "=r"(r[2]), "=r"(r[3]) : "r"(addr));
}

__device__ __forceinline__ void mma_bf16(float c[4], const uint32_t a[4],
                                         uint32_t b0, uint32_t b1) {
    asm volatile(
        "mma.sync.aligned.m16n8k16.row.col.f32.bf16.bf16.f32 "
        "{%0,%1,%2,%3}, {%4,%5,%6,%7}, {%8,%9}, {%0,%1,%2,%3};"
        : "+f"(c[0]), "+f"(c[1]), "+f"(c[2]), "+f"(c[3])
        : "r"(a[0]), "r"(a[1]), "r"(a[2]), "r"(a[3]), "r"(b0), "r"(b1));
}

// split two floats: hi = truncated-bf16 pair, lo = rn-bf16 of residual
__device__ __forceinline__ void split2(float a, float b,
                                       uint32_t& hi, uint32_t& lo) {
    uint32_t ua = __float_as_uint(a), ub = __float_as_uint(b);
    asm("prmt.b32 %0, %1, %2, 0x7632;" : "=r"(hi) : "r"(ua), "r"(ub));
    float ra = a - __uint_as_float(ua & 0xFFFF0000u);
    float rb = b - __uint_as_float(ub & 0xFFFF0000u);
    asm("cvt.rn.bf16x2.f32 %0, %1, %2;" : "=r"(lo) : "f"(rb), "f"(ra));
}
__device__ __forceinline__ void split4(const float4& f, uint2& hp, uint2& lp) {
    split2(f.x, f.y, hp.x, lp.x);
    split2(f.z, f.w, hp.y, lp.y);
}

__global__ __launch_bounds__(256, 3)
void gat_hmma_kernel(const float* __restrict__ x,
                     const float* __restrict__ W,
                     const float* __restrict__ self_weight,
                     float* __restrict__ out) {
    extern __shared__ char smem[];
    const uint32_t sbase = smem_u32(smem);
    const int tid = threadIdx.x;
    const int wid = tid >> 5;
    const int lid = tid & 31;

    const int bcol = blockIdx.x & 1;
    const int brow = blockIdx.x >> 1;
    const int row0 = brow * TM;
    const int col0 = bcol * TN;

    const float s = 1.0f + self_weight[0];

    // ---- batched loads: 12 LDG.128 in flight before any convert ----
    float4 fa[4], fb[8];
    #pragma unroll
    for (int r = 0; r < 4; r++) {
        int g  = tid + r * 256;
        int m  = g >> 5;                  // 0..31
        int k4 = g & 31;
        fa[r] = *(const float4*)&x[(size_t)(row0 + m) * KDIM + k4 * 4];
    }
    #pragma unroll
    for (int r = 0; r < 8; r++) {
        int g  = tid + r * 256;
        int k  = g >> 4;                  // 0..127
        int n4 = g & 15;
        fb[r] = *(const float4*)&W[(size_t)k * NDIM + col0 + n4 * 4];
    }

    // ---- convert + store A ----
    #pragma unroll
    for (int r = 0; r < 4; r++) {
        int g  = tid + r * 256;
        int m  = g >> 5;
        int k4 = g & 31;
        uint2 hp, lp;
        split4(fa[r], hp, lp);
        *(uint2*)(smem + SMEM_AH + m * ASTRIDE + k4 * 8) = hp;
        *(uint2*)(smem + SMEM_AL + m * ASTRIDE + k4 * 8) = lp;
    }
    // ---- convert + store B ----
    #pragma unroll
    for (int r = 0; r < 8; r++) {
        int g  = tid + r * 256;
        int k  = g >> 4;
        int n4 = g & 15;
        uint2 hp, lp;
        split4(fb[r], hp, lp);
        *(uint2*)(smem + SMEM_BH + k * BSTRIDE + n4 * 8) = hp;
        *(uint2*)(smem + SMEM_BL + k * BSTRIDE + n4 * 8) = lp;
    }
    __syncthreads();

    // ---- compute: warp tile 16 rows x 16 cols (2x4 warp grid) ----
    const int wm = (wid >> 2) * 16;     // 0,16
    const int wn = (wid & 3) * 16;      // 0,16,32,48

    float hh[2][4], hl[2][4], lh[2][4];
    #pragma unroll
    for (int j = 0; j < 2; j++)
        #pragma unroll
        for (int e = 0; e < 4; e++) { hh[j][e] = 0.f; hl[j][e] = 0.f; lh[j][e] = 0.f; }

    // A x4 (non-trans) from [m][k]
    const uint32_t aAddr = sbase + SMEM_AH
        + (wm + (lid & 15)) * ASTRIDE + 16 * (lid >> 4);
    // B x4 trans from [k][n]: covers n0-15 x k0-15 of this warp's n tile
    const uint32_t bAddr = sbase + SMEM_BH
        + (8 * ((lid >> 3) & 1) + (lid & 7)) * BSTRIDE
        + (wn + 8 * (lid >> 4)) * 2;

    const uint32_t dAL = SMEM_AL - SMEM_AH;
    const uint32_t dBL = SMEM_BL - SMEM_BH;

    #pragma unroll
    for (int ks = 0; ks < 8; ks++) {
        const uint32_t ako = ks * 32;            // 16 bf16 along A row
        const uint32_t bko = ks * 16 * BSTRIDE;  // 16 k-rows down B tile

        uint32_t ah[4], al[4];
        ldsm4(ah, aAddr + ako);
        ldsm4(al, aAddr + ako + dAL);

        uint32_t bh[4], bl[4];  // {n0-7k0-7, n0-7k8-15, n8-15k0-7, n8-15k8-15}
        ldsm4t(bh, bAddr + bko);
        ldsm4t(bl, bAddr + bko + dBL);

        #pragma unroll
        for (int nt = 0; nt < 2; nt++) {
            const int q = nt * 2;
            mma_bf16(hh[nt], ah, bh[q], bh[q + 1]);
            mma_bf16(hl[nt], ah, bl[q], bl[q + 1]);
            mma_bf16(lh[nt], al, bh[q], bh[q + 1]);
        }
    }

    // ---- epilogue: combine terms, scale, store ----
    #pragma unroll
    for (int nt = 0; nt < 2; nt++) {
        const int r0 = row0 + wm + (lid >> 2);
        const int c  = col0 + wn + 8 * nt + 2 * (lid & 3);
        float v0 = (hh[nt][0] + hl[nt][0] + lh[nt][0]) * s;
        float v1 = (hh[nt][1] + hl[nt][1] + lh[nt][1]) * s;
        float v2 = (hh[nt][2] + hl[nt][2] + lh[nt][2]) * s;
        float v3 = (hh[nt][3] + hl[nt][3] + lh[nt][3]) * s;
        float2 s0 = {v0, v1};
        float2 s1 = {v2, v3};
        *(float2*)&out[(size_t)r0 * NDIM + c]       = s0;
        *(float2*)&out[(size_t)(r0 + 8) * NDIM + c] = s1;
    }
}

extern "C" void kernel_launch(void* const* d_in, const int* in_sizes, int n_in,
                              void* d_out, int out_size) {
    // metadata order: x, adj (UNUSED), W, att (UNUSED), self_weight
    const float* x  = (const float*)d_in[0];
    const float* W  = (const float*)d_in[2];
    const float* sw = (const float*)d_in[4];
    float* out      = (float*)d_out;

    cudaFuncSetAttribute(gat_hmma_kernel,
                         cudaFuncAttributeMaxDynamicSharedMemorySize, SMEM_TOTAL);

    const int M = in_sizes[0] / KDIM;             // 8192
    dim3 grid((M / TM) * (NDIM / TN));            // 256 * 2 = 512 blocks
    gat_hmma_kernel<<<grid, 256, SMEM_TOTAL>>>(x, W, sw, out);
}

// round 8
// speedup vs baseline: 1.2657x; 1.2657x over previous
#include <cuda_runtime.h>
#include <cuda_fp16.h>
#include <cstdint>

// Problem (fixed): B=4,N=2048,Fin=128,H=4,Fout=32.
// Identity: softmax(scores,m).sum(m)==1  =>  out = (1+self_weight)*(x @ W).
// adj, att are dead inputs.
//
// R8: 2-term fp16 HMMA:  out ~= xh*(wh + wl)
//   x -> single fp16 (err 2^-12, RMS-attenuated over K=128 -> ~1e-4)
//   W -> exact 2-term fp16 split (wh + wl)
// vs R6: MMAs 96->64/warp, A smem+convert halved, same R6 tiling
// (TM=64, TN=64, grid 256, occ 2) which was empirically best.

#define KDIM 128
#define NDIM 128
#define TM 64
#define TN 64
#define ASTRIDE 272   // A row: 128 fp16 = 256B data + 16 pad
#define BSTRIDE 144   // B row: 64 fp16 = 128B data + 16 pad

#define SMEM_A  0
#define SMEM_BH (SMEM_A + TM * ASTRIDE)         // 17408
#define SMEM_BL (SMEM_BH + KDIM * BSTRIDE)      // 35840
#define SMEM_TOTAL (SMEM_BL + KDIM * BSTRIDE)   // 54272

__device__ __forceinline__ uint32_t smem_u32(const void* p) {
    uint32_t a;
    asm("{ .reg .u64 t; cvta.to.shared.u64 t, %1; cvt.u32.u64 %0, t; }"
        : "=r"(a) : "l"(p));
    return a;
}

__device__ __forceinline__ void ldsm4(uint32_t r[4], uint32_t addr) {
    asm volatile("ldmatrix.sync.aligned.m8n8.x4.shared.b16 {%0,%1,%2,%3}, [%4];"
                 : "=r"(r[0]), "=r"(r[1]), "=r"(r[2]), "=r"(r[3]) : "r"(addr));
}
__device__ __forceinline__ void ldsm4t(uint32_t r[4], uint32_t addr) {
    asm volatile("ldmatrix.sync.aligned.m8n8.x4.trans.shared.b16 {%0,%1,%2,%3}, [%4];"
                 : "=r"(r[0]), "=r"(r[1]), "=r"(r[2]), "=r"(r[3]) : "r"(addr));
}

__device__ __forceinline__ void mma_f16(float c[4], const uint32_t a[4],
                                        uint32_t b0, uint32_t b1) {
    asm volatile(
        "mma.sync.aligned.m16n8k16.row.col.f32.f16.f16.f32 "
        "{%0,%1,%2,%3}, {%4,%5,%6,%7}, {%8,%9}, {%0,%1,%2,%3};"
        : "+f"(c[0]), "+f"(c[1]), "+f"(c[2]), "+f"(c[3])
        : "r"(a[0]), "r"(a[1]), "r"(a[2]), "r"(a[3]), "r"(b0), "r"(b1));
}

// fp16 conversions
__device__ __forceinline__ uint32_t h2_pack(float a, float b) {
    __half2 h = __float22half2_rn(make_float2(a, b));   // x=a(low), y=b(high)
    return *reinterpret_cast<uint32_t*>(&h);
}
// A: single-term fp16 of a float4 -> uint2
__device__ __forceinline__ uint2 cvt4(const float4& f) {
    uint2 r;
    r.x = h2_pack(f.x, f.y);
    r.y = h2_pack(f.z, f.w);
    return r;
}
// W: exact 2-term split of a float4
__device__ __forceinline__ void split4w(const float4& f, uint2& hp, uint2& lp) {
    __half2 h01 = __float22half2_rn(make_float2(f.x, f.y));
    __half2 h23 = __float22half2_rn(make_float2(f.z, f.w));
    float r0 = f.x - __half2float(h01.x);
    float r1 = f.y - __half2float(h01.y);
    float r2 = f.z - __half2float(h23.x);
    float r3 = f.w - __half2float(h23.y);
    hp.x = *reinterpret_cast<uint32_t*>(&h01);
    hp.y = *reinterpret_cast<uint32_t*>(&h23);
    lp.x = h2_pack(r0, r1);
    lp.y = h2_pack(r2, r3);
}

__global__ __launch_bounds__(256, 2)
void gat_hmma_kernel(const float* __restrict__ x,
                     const float* __restrict__ W,
                     const float* __restrict__ self_weight,
                     float* __restrict__ out) {
    extern __shared__ char smem[];
    const uint32_t sbase = smem_u32(smem);
    const int tid = threadIdx.x;
    const int wid = tid >> 5;
    const int lid = tid & 31;

    const int bcol = blockIdx.x & 1;
    const int brow = blockIdx.x >> 1;
    const int row0 = brow * TM;
    const int col0 = bcol * TN;

    const float s = 1.0f + self_weight[0];

    // ---- batched loads: all 16 LDG.128 in flight before any convert ----
    float4 fa[8], fb[8];
    #pragma unroll
    for (int r = 0; r < 8; r++) {
        int g  = tid + r * 256;
        int m  = g >> 5;                  // 0..63
        int k4 = g & 31;
        fa[r] = *(const float4*)&x[(size_t)(row0 + m) * KDIM + k4 * 4];
    }
    #pragma unroll
    for (int r = 0; r < 8; r++) {
        int g  = tid + r * 256;
        int k  = g >> 4;                  // 0..127
        int n4 = g & 15;
        fb[r] = *(const float4*)&W[(size_t)k * NDIM + col0 + n4 * 4];
    }

    // ---- convert + store A (single fp16 term) ----
    #pragma unroll
    for (int r = 0; r < 8; r++) {
        int g  = tid + r * 256;
        int m  = g >> 5;
        int k4 = g & 31;
        *(uint2*)(smem + SMEM_A + m * ASTRIDE + k4 * 8) = cvt4(fa[r]);
    }
    // ---- convert + store B (2-term fp16 split) ----
    #pragma unroll
    for (int r = 0; r < 8; r++) {
        int g  = tid + r * 256;
        int k  = g >> 4;
        int n4 = g & 15;
        uint2 hp, lp;
        split4w(fb[r], hp, lp);
        *(uint2*)(smem + SMEM_BH + k * BSTRIDE + n4 * 8) = hp;
        *(uint2*)(smem + SMEM_BL + k * BSTRIDE + n4 * 8) = lp;
    }
    __syncthreads();

    // ---- compute: warp tile 16 rows x 32 cols (4x2 warp grid) ----
    const int wm = (wid >> 1) * 16;     // 0,16,32,48
    const int wn = (wid & 1) * 32;      // 0,32

    float t0[4][4], t1[4][4];
    #pragma unroll
    for (int j = 0; j < 4; j++)
        #pragma unroll
        for (int e = 0; e < 4; e++) { t0[j][e] = 0.f; t1[j][e] = 0.f; }

    // A x4 (non-trans) from [m][k]
    const uint32_t aAddr = sbase + SMEM_A
        + (wm + (lid & 15)) * ASTRIDE + 16 * (lid >> 4);
    // B x4 trans from [k][n]
    uint32_t bAddr[2];
    #pragma unroll
    for (int p = 0; p < 2; p++)
        bAddr[p] = sbase + SMEM_BH
            + (8 * ((lid >> 3) & 1) + (lid & 7)) * BSTRIDE
            + (wn + 16 * p + 8 * (lid >> 4)) * 2;

    const uint32_t dBL = SMEM_BL - SMEM_BH;

    #pragma unroll
    for (int ks = 0; ks < 8; ks++) {
        const uint32_t ako = ks * 32;            // 16 fp16 along A row
        const uint32_t bko = ks * 16 * BSTRIDE;  // 16 k-rows down B tile

        uint32_t ah[4];
        ldsm4(ah, aAddr + ako);

        uint32_t bh[2][4], bl[2][4];
        #pragma unroll
        for (int p = 0; p < 2; p++) {
            ldsm4t(bh[p], bAddr[p] + bko);
            ldsm4t(bl[p], bAddr[p] + bko + dBL);
        }

        #pragma unroll
        for (int nt = 0; nt < 4; nt++) {
            const int p = nt >> 1, q = (nt & 1) * 2;
            mma_f16(t0[nt], ah, bh[p][q], bh[p][q + 1]);  // xh*wh
            mma_f16(t1[nt], ah, bl[p][q], bl[p][q + 1]);  // xh*wl
        }
    }

    // ---- epilogue: combine terms, scale, store ----
    #pragma unroll
    for (int nt = 0; nt < 4; nt++) {
        const int r0 = row0 + wm + (lid >> 2);
        const int c  = col0 + wn + 8 * nt + 2 * (lid & 3);
        float v0 = (t0[nt][0] + t1[nt][0]) * s;
        float v1 = (t0[nt][1] + t1[nt][1]) * s;
        float v2 = (t0[nt][2] + t1[nt][2]) * s;
        float v3 = (t0[nt][3] + t1[nt][3]) * s;
        float2 s0 = {v0, v1};
        float2 s1 = {v2, v3};
        *(float2*)&out[(size_t)r0 * NDIM + c]       = s0;
        *(float2*)&out[(size_t)(r0 + 8) * NDIM + c] = s1;
    }
}

extern "C" void kernel_launch(void* const* d_in, const int* in_sizes, int n_in,
                              void* d_out, int out_size) {
    // metadata order: x, adj (UNUSED), W, att (UNUSED), self_weight
    const float* x  = (const float*)d_in[0];
    const float* W  = (const float*)d_in[2];
    const float* sw = (const float*)d_in[4];
    float* out      = (float*)d_out;

    cudaFuncSetAttribute(gat_hmma_kernel,
                         cudaFuncAttributeMaxDynamicSharedMemorySize, SMEM_TOTAL);

    const int M = in_sizes[0] / KDIM;             // 8192
    dim3 grid((M / TM) * (NDIM / TN));            // 128 * 2 = 256 blocks
    gat_hmma_kernel<<<grid, 256, SMEM_TOTAL>>>(x, W, sw, out);
}